// round 1
// baseline (speedup 1.0000x reference)
#include <cuda_runtime.h>
#include <cuda_bf16.h>

#define TICKS   1000
#define NTAPS   49
#define KW      7
#define OUT_CH  128
#define MAXD    14          // 6 + min(stride,8)
#define MAXC    (MAXD*MAXD) // 196
#define GPITCH  1024

// ---- scratch (no allocations allowed) ----
__device__ float d_hist[TICKS * MAXC];     // hist[t*C + cls]
__device__ float d_WcT[MAXC * OUT_CH];     // WcT[cls*128 + c]
__device__ float d_g[OUT_CH * GPITCH];     // gd[c][t] = g[c][t-1], gd[c][0]=0

__device__ __forceinline__ int imin(int a, int b) { return a < b ? a : b; }

// ------------------------------------------------------------------
// 0) zero scratch (hist + g). 196000 and 131072 floats.
// ------------------------------------------------------------------
__global__ void zero_kernel() {
    int i = blockIdx.x * blockDim.x + threadIdx.x;
    if (i < TICKS * MAXC)      d_hist[i] = 0.f;
    if (i < OUT_CH * GPITCH)   d_g[i]    = 0.f;
}

// ------------------------------------------------------------------
// 1) event scatter into class histogram.
//    class_x = x<6 ? x : 6 + min(x%stride, 7); D = 6+min(stride,8); C = D*D
//    Hot path (x>=6 && y>=6, stride<=2): shared-mem atomics, flushed once.
// ------------------------------------------------------------------
__global__ void __launch_bounds__(512) scatter_kernel(
    const int* __restrict__ tk, const int* __restrict__ xs,
    const int* __restrict__ ys, const float* __restrict__ vs,
    const int* __restrict__ sp, int n)
{
    __shared__ float sh[4 * TICKS];            // up to stride^2=4 hot classes
    const int stride = *sp;
    const int D  = 6 + imin(stride, 8);
    const int C  = D * D;
    const int S2 = stride * stride;
    const bool hot = (stride <= 2);

    if (hot) {
        for (int i = threadIdx.x; i < S2 * TICKS; i += blockDim.x) sh[i] = 0.f;
    }
    __syncthreads();

    const int tid = blockIdx.x * blockDim.x + threadIdx.x;
    const int nth = gridDim.x * blockDim.x;

    auto proc = [&](int t, int x, int y, float v) {
        if (stride == 2) {                      // fast path (uniform branch)
            if (x >= 6 && y >= 6) {
                atomicAdd(&sh[t * 4 + ((y & 1) << 1) + (x & 1)], v);
            } else {
                int cx = (x >= 6) ? 6 + (x & 1) : x;
                int cy = (y >= 6) ? 6 + (y & 1) : y;
                atomicAdd(&d_hist[t * C + cy * D + cx], v);
            }
        } else {
            int rx = x % stride, ry = y % stride;
            if (hot && x >= 6 && y >= 6) {
                atomicAdd(&sh[t * S2 + ry * stride + rx], v);
            } else {
                int cx = (x >= 6) ? 6 + imin(rx, 7) : x;
                int cy = (y >= 6) ? 6 + imin(ry, 7) : y;
                atomicAdd(&d_hist[t * C + cy * D + cx], v);
            }
        }
    };

    const int n4 = n >> 2;
    const int4*   t4 = reinterpret_cast<const int4*>(tk);
    const int4*   x4 = reinterpret_cast<const int4*>(xs);
    const int4*   y4 = reinterpret_cast<const int4*>(ys);
    const float4* v4 = reinterpret_cast<const float4*>(vs);

    for (int i = tid; i < n4; i += nth) {
        int4   a = t4[i];
        int4   b = x4[i];
        int4   c = y4[i];
        float4 w = v4[i];
        proc(a.x, b.x, c.x, w.x);
        proc(a.y, b.y, c.y, w.y);
        proc(a.z, b.z, c.z, w.z);
        proc(a.w, b.w, c.w, w.w);
    }
    for (int i = (n4 << 2) + tid; i < n; i += nth)
        proc(tk[i], xs[i], ys[i], vs[i]);

    __syncthreads();
    if (hot) {
        for (int i = threadIdx.x; i < S2 * TICKS; i += blockDim.x) {
            float val = sh[i];
            if (val != 0.f) {
                int t   = i / S2;
                int hid = i - t * S2;
                int ry  = hid / stride;
                int rx  = hid - ry * stride;
                atomicAdd(&d_hist[t * C + (6 + ry) * D + (6 + rx)], val);
            }
        }
    }
}

// ------------------------------------------------------------------
// 2) class weights: WcT[cls][c] = sum over taps valid for that class.
// ------------------------------------------------------------------
__global__ void wclass_kernel(const float* __restrict__ w, const int* __restrict__ sp)
{
    const int stride = *sp;
    const int D = 6 + imin(stride, 8);
    const int cls = blockIdx.x;
    if (cls >= D * D) return;
    const int cy = cls / D, cx = cls % D;
    const int c  = threadIdx.x;

    int sx, lx, sy, ly;
    if (cx < 6) { sx = cx % stride; lx = cx; } else { sx = cx - 6; lx = 6; }
    if (cy < 6) { sy = cy % stride; ly = cy; } else { sy = cy - 6; ly = 6; }

    float acc = 0.f;
    for (int ky = sy; ky <= ly; ky += stride)
        for (int kx = sx; kx <= lx; kx += stride)
            acc += w[c * NTAPS + ky * KW + kx];
    d_WcT[cls * OUT_CH + c] = acc;
}

// ------------------------------------------------------------------
// 3) class GEMM: gd[c][t+1] = sum_cls WcT[cls][c] * hist[t][cls]
//    block = one tick, thread = channel.
// ------------------------------------------------------------------
__global__ void __launch_bounds__(OUT_CH) gemm_kernel(const int* __restrict__ sp)
{
    const int stride = *sp;
    const int D = 6 + imin(stride, 8);
    const int C = D * D;
    const int t = blockIdx.x;
    const int c = threadIdx.x;

    const float* __restrict__ hrow = d_hist + (size_t)t * C;
    float acc = 0.f;
    int cls = 0;
    for (; cls + 4 <= C; cls += 4) {
        float h0 = __ldg(&hrow[cls + 0]);
        float h1 = __ldg(&hrow[cls + 1]);
        float h2 = __ldg(&hrow[cls + 2]);
        float h3 = __ldg(&hrow[cls + 3]);
        acc = fmaf(d_WcT[(cls + 0) * OUT_CH + c], h0, acc);
        acc = fmaf(d_WcT[(cls + 1) * OUT_CH + c], h1, acc);
        acc = fmaf(d_WcT[(cls + 2) * OUT_CH + c], h2, acc);
        acc = fmaf(d_WcT[(cls + 3) * OUT_CH + c], h3, acc);
    }
    for (; cls < C; ++cls)
        acc = fmaf(d_WcT[cls * OUT_CH + c], __ldg(&hrow[cls]), acc);

    d_g[c * GPITCH + t + 1] = acc;   // 1-tick synaptic delay baked in
}

// ------------------------------------------------------------------
// 4) Izhikevich sim: one warp per channel; serial over ticks.
//    out[0][c][t] = spike, out[1][c][t] = v (post-reset).
// ------------------------------------------------------------------
__global__ void __launch_bounds__(32) sim_kernel(float* __restrict__ out)
{
    const int c    = blockIdx.x;
    const int lane = threadIdx.x;
    const float* __restrict__ grow = d_g + c * GPITCH;
    float* __restrict__ ospk = out + c * TICKS;
    float* __restrict__ ovtr = out + OUT_CH * TICKS + c * TICKS;

    const float decay = 0.9f;                        // 1 - dt/tau_fall
    const float h     = (float)(0.001 / 150.0);      // dt / C
    const float Kp = 1.2f, VR = -75.f, VT = -45.f;
    const float AP = 0.01f, BP = 5.f, VP = 50.f;
    const float DP = 130.f, VRS = -56.f, IIN = 350.f, DT = 0.001f;

    float v = VR, u = 0.f, S = 0.f;
    __shared__ float shg[32], shv[32], shs[32];

    for (int t0 = 0; t0 < TICKS; t0 += 32) {
        shg[lane] = grow[t0 + lane];                 // GPITCH pad is zeroed
        __syncwarp();
        #pragma unroll 8
        for (int i = 0; i < 32; ++i) {
            float gt = shg[i];
            S = S * decay + gt;                      // summed synapse state
            float I = IIN + S;                       // I_bias = 0
            v = v + (Kp * (v - VR) * (v - VT) - u + I) * h;
            u = u + AP * (BP * (v - VR) - u) * DT;   // uses pre-reset v
            bool sp = v >= VP;
            float spf = sp ? 1.f : 0.f;
            if (sp) { v = VRS; u = u + DP; }
            if (lane == 0) { shv[i] = v; shs[i] = spf; }
        }
        __syncwarp();
        int t = t0 + lane;
        if (t < TICKS) { ospk[t] = shs[lane]; ovtr[t] = shv[lane]; }
        __syncwarp();
    }
}

// ------------------------------------------------------------------
extern "C" void kernel_launch(void* const* d_in, const int* in_sizes, int n_in,
                              void* d_out, int out_size)
{
    const int*   tk = (const int*)  d_in[0];   // spike_ticks
    const int*   xs = (const int*)  d_in[1];   // spike_x
    const int*   ys = (const int*)  d_in[2];   // spike_y
    const float* vs = (const float*)d_in[3];   // spike_values
    const float* w  = (const float*)d_in[4];   // weights [128,49]
    const int*   sp = (const int*)  d_in[5];   // stride
    const int    n  = in_sizes[0];

    zero_kernel<<<(TICKS * MAXC + 255) / 256, 256>>>();
    scatter_kernel<<<148, 512>>>(tk, xs, ys, vs, sp, n);
    wclass_kernel<<<MAXC, OUT_CH>>>(w, sp);
    gemm_kernel<<<TICKS, OUT_CH>>>(sp);
    sim_kernel<<<OUT_CH, 32>>>((float*)d_out);
}

// round 4
// speedup vs baseline: 1.2317x; 1.2317x over previous
#include <cuda_runtime.h>
#include <cuda_bf16.h>

#define TICKS   1000
#define TPAD    1024        // TICKS rounded up to 32 — sim chunks read the pad
#define NTAPS   49
#define KW      7
#define OUT_CH  128
#define MAXD    14          // 6 + min(stride,8)
#define MAXC    (MAXD*MAXD) // 196

// ---- scratch (no allocations allowed) ----
// __align__(16) is load-bearing: Phase B of sim_kernel does float4 loads of rows.
__device__ __align__(16) float d_hist[TICKS * MAXC];   // hist[t*C + cls]

__device__ __forceinline__ int imin(int a, int b) { return a < b ? a : b; }

// ------------------------------------------------------------------
// 0) zero hist scratch.
// ------------------------------------------------------------------
__global__ void zero_kernel() {
    int i = blockIdx.x * blockDim.x + threadIdx.x;
    if (i < TICKS * MAXC) d_hist[i] = 0.f;
}

// ------------------------------------------------------------------
// 1) event scatter into class histogram.
//    class_x = x<6 ? x : 6 + min(x%stride, 7); D = 6+min(stride,8); C = D*D
//    Hot classes (x>=6 && y>=6, stride<=2): per-CTA shared-mem atomics,
//    flushed once with global atomics.
// ------------------------------------------------------------------
__global__ void __launch_bounds__(1024) scatter_kernel(
    const int* __restrict__ tk, const int* __restrict__ xs,
    const int* __restrict__ ys, const float* __restrict__ vs,
    const int* __restrict__ sp, int n)
{
    __shared__ float sh[4 * TICKS];            // up to stride^2=4 hot classes
    const int stride = *sp;
    const int D  = 6 + imin(stride, 8);
    const int C  = D * D;
    const int S2 = stride * stride;
    const bool hot = (stride <= 2);

    if (hot) {
        for (int i = threadIdx.x; i < S2 * TICKS; i += blockDim.x) sh[i] = 0.f;
    }
    __syncthreads();

    const int tid = blockIdx.x * blockDim.x + threadIdx.x;
    const int nth = gridDim.x * blockDim.x;

    auto proc = [&](int t, int x, int y, float v) {
        if (stride == 2) {                      // fast path (uniform branch)
            if (x >= 6 && y >= 6) {
                atomicAdd(&sh[t * 4 + ((y & 1) << 1) + (x & 1)], v);
            } else {
                int cx = (x >= 6) ? 6 + (x & 1) : x;
                int cy = (y >= 6) ? 6 + (y & 1) : y;
                atomicAdd(&d_hist[t * C + cy * D + cx], v);
            }
        } else {
            int rx = x % stride, ry = y % stride;
            if (hot && x >= 6 && y >= 6) {
                atomicAdd(&sh[t * S2 + ry * stride + rx], v);
            } else {
                int cx = (x >= 6) ? 6 + imin(rx, 7) : x;
                int cy = (y >= 6) ? 6 + imin(ry, 7) : y;
                atomicAdd(&d_hist[t * C + cy * D + cx], v);
            }
        }
    };

    const int n4 = n >> 2;
    const int4*   t4 = reinterpret_cast<const int4*>(tk);
    const int4*   x4 = reinterpret_cast<const int4*>(xs);
    const int4*   y4 = reinterpret_cast<const int4*>(ys);
    const float4* v4 = reinterpret_cast<const float4*>(vs);

    for (int i = tid; i < n4; i += nth) {
        int4   a = t4[i];
        int4   b = x4[i];
        int4   c = y4[i];
        float4 w = v4[i];
        proc(a.x, b.x, c.x, w.x);
        proc(a.y, b.y, c.y, w.y);
        proc(a.z, b.z, c.z, w.z);
        proc(a.w, b.w, c.w, w.w);
    }
    for (int i = (n4 << 2) + tid; i < n; i += nth)
        proc(tk[i], xs[i], ys[i], vs[i]);

    __syncthreads();
    if (hot) {
        for (int i = threadIdx.x; i < S2 * TICKS; i += blockDim.x) {
            float val = sh[i];
            if (val != 0.f) {
                int t   = i / S2;
                int hid = i - t * S2;
                int ry  = hid / stride;
                int rx  = hid - ry * stride;
                atomicAdd(&d_hist[t * C + (6 + ry) * D + (6 + rx)], val);
            }
        }
    }
}

// ------------------------------------------------------------------
// 2) fused drive + Izhikevich sim. One block per channel.
//    Phase A: build class weights (shared).
//    Phase B: 128 threads compute delayed drive g[t] = wc . hist[t-1]
//             into sg[0..TPAD), pad zero-filled (sim chunks read the pad).
//    Phase C: warp 0 runs the serial neuron recurrence; stores guarded
//             to t < TICKS (TICKS is not a multiple of 32!).
// ------------------------------------------------------------------
__global__ void __launch_bounds__(128) sim_kernel(
    const float* __restrict__ w, const int* __restrict__ sp,
    float* __restrict__ out)
{
    __shared__ __align__(16) float wc[MAXC];
    __shared__ float sg[TPAD];

    const int c   = blockIdx.x;
    const int tid = threadIdx.x;
    const int stride = *sp;
    const int D = 6 + imin(stride, 8);
    const int C = D * D;

    // ---- Phase A: class weights for this channel ----
    for (int cls = tid; cls < C; cls += blockDim.x) {
        const int cy = cls / D, cx = cls % D;
        int sx, lx, sy, ly;
        if (cx < 6) { sx = cx % stride; lx = cx; } else { sx = cx - 6; lx = 6; }
        if (cy < 6) { sy = cy % stride; ly = cy; } else { sy = cy - 6; ly = 6; }
        float acc = 0.f;
        for (int ky = sy; ky <= ly; ky += stride)
            for (int kx = sx; kx <= lx; kx += stride)
                acc += w[c * NTAPS + ky * KW + kx];
        wc[cls] = acc;
    }
    __syncthreads();

    // ---- Phase B: delayed drive g[t] = dot(wc, hist[t-1]); g[0]=0; pad=0 ----
    if ((C & 3) == 0) {
        const int C4 = C >> 2;
        const float4* __restrict__ wr = reinterpret_cast<const float4*>(wc);
        for (int t = tid; t < TPAD; t += blockDim.x) {
            float acc = 0.f;
            if (t > 0 && t < TICKS) {
                const float4* __restrict__ hr =
                    reinterpret_cast<const float4*>(d_hist + (size_t)(t - 1) * C);
                #pragma unroll 4
                for (int q = 0; q < C4; ++q) {
                    float4 h  = __ldg(&hr[q]);
                    float4 ww = wr[q];
                    acc = fmaf(ww.x, h.x, acc);
                    acc = fmaf(ww.y, h.y, acc);
                    acc = fmaf(ww.z, h.z, acc);
                    acc = fmaf(ww.w, h.w, acc);
                }
            }
            sg[t] = acc;
        }
    } else {
        for (int t = tid; t < TPAD; t += blockDim.x) {
            float acc = 0.f;
            if (t > 0 && t < TICKS) {
                const float* __restrict__ hr = d_hist + (size_t)(t - 1) * C;
                #pragma unroll 7
                for (int cls = 0; cls < C; ++cls)
                    acc = fmaf(wc[cls], __ldg(&hr[cls]), acc);
            }
            sg[t] = acc;
        }
    }
    __syncthreads();

    // ---- Phase C: serial sim, warp 0 only ----
    if (tid >= 32) return;
    const int lane = tid;

    float* __restrict__ ospk = out + c * TICKS;
    float* __restrict__ ovtr = out + OUT_CH * TICKS + c * TICKS;

    const float decay = 0.9f;                        // 1 - dt/tau_fall
    const float h     = (float)(0.001 / 150.0);      // dt / C
    const float Kp = 1.2f, VR = -75.f, VT = -45.f;
    const float AP = 0.01f, BP = 5.f, VP = 50.f;
    const float DP = 130.f, VRS = -56.f, IIN = 350.f, DT = 0.001f;

    float v = VR, u = 0.f, S = 0.f;

    for (int t0 = 0; t0 < TICKS; t0 += 32) {
        float keepv = 0.f, keeps = 0.f;
        #pragma unroll
        for (int i = 0; i < 32; ++i) {
            float gt = sg[t0 + i];                   // pad reads are zeros
            S = S * decay + gt;                      // summed synapse state
            float I = IIN + S;                       // I_bias = 0
            v = v + (Kp * (v - VR) * (v - VT) - u + I) * h;
            u = u + AP * (BP * (v - VR) - u) * DT;   // uses pre-reset v
            bool sp = v >= VP;
            float spf = sp ? 1.f : 0.f;
            if (sp) { v = VRS; u = u + DP; }
            keepv = (lane == i) ? v   : keepv;       // register-keep, off chain
            keeps = (lane == i) ? spf : keeps;
        }
        int t = t0 + lane;
        if (t < TICKS) {                             // guard: 1000 % 32 != 0
            ospk[t] = keeps;                         // coalesced per chunk
            ovtr[t] = keepv;
        }
    }
}

// ------------------------------------------------------------------
extern "C" void kernel_launch(void* const* d_in, const int* in_sizes, int n_in,
                              void* d_out, int out_size)
{
    const int*   tk = (const int*)  d_in[0];   // spike_ticks
    const int*   xs = (const int*)  d_in[1];   // spike_x
    const int*   ys = (const int*)  d_in[2];   // spike_y
    const float* vs = (const float*)d_in[3];   // spike_values
    const float* w  = (const float*)d_in[4];   // weights [128,49]
    const int*   sp = (const int*)  d_in[5];   // stride
    const int    n  = in_sizes[0];

    zero_kernel<<<(TICKS * MAXC + 255) / 256, 256>>>();
    scatter_kernel<<<148, 1024>>>(tk, xs, ys, vs, sp, n);
    sim_kernel<<<OUT_CH, 128>>>(w, sp, (float*)d_out);
}